// round 2
// baseline (speedup 1.0000x reference)
#include <cuda_runtime.h>
#include <cstdint>

#define Bt   128
#define Tt   512
#define Et   256
#define Ht   512
#define VCt  64
#define VPt  128
#define NCTA 128

// ---------------- persistent device scratch (no allocs allowed) ----------------
__device__ float g_P[VCt * Ht];            // emb_table @ W_xh0 + b_xh0  (64 x 512)
__device__ float g_h0[2][Ht * Bt];         // layer0 hidden, [j][b], double buffered
__device__ float g_h1[2][Ht * Bt];         // layer1 hidden
__device__ float g_ysT[(size_t)Tt * Ht * Bt]; // outputs, [t][j][b]  (128 MB)
__device__ unsigned g_count = 0;
__device__ unsigned g_sense = 0;

// ---------------- kernel 1: P = emb_table @ W_xh0 + b_xh0 ----------------
__global__ __launch_bounds__(128) void proj_kernel(
    const float* __restrict__ emb, const float* __restrict__ Wxh0,
    const float* __restrict__ bxh0) {
  __shared__ float esh[Et];
  int v = blockIdx.x;
  for (int i = threadIdx.x; i < Et; i += 128) esh[i] = emb[v * Et + i];
  __syncthreads();
  for (int j = threadIdx.x; j < Ht; j += 128) {
    float s = bxh0[j];
#pragma unroll 8
    for (int e = 0; e < Et; ++e) s = fmaf(esh[e], Wxh0[e * Ht + j], s);
    g_P[v * Ht + j] = s;
  }
}

__device__ __forceinline__ void fma16(float4& a0, float4& a1, float4& a2,
                                      float4& a3, const float4 w,
                                      const float4 hv) {
  a0.x = fmaf(w.x, hv.x, a0.x); a0.y = fmaf(w.x, hv.y, a0.y);
  a0.z = fmaf(w.x, hv.z, a0.z); a0.w = fmaf(w.x, hv.w, a0.w);
  a1.x = fmaf(w.y, hv.x, a1.x); a1.y = fmaf(w.y, hv.y, a1.y);
  a1.z = fmaf(w.y, hv.z, a1.z); a1.w = fmaf(w.y, hv.w, a1.w);
  a2.x = fmaf(w.z, hv.x, a2.x); a2.y = fmaf(w.z, hv.y, a2.y);
  a2.z = fmaf(w.z, hv.z, a2.z); a2.w = fmaf(w.z, hv.w, a2.w);
  a3.x = fmaf(w.w, hv.x, a3.x); a3.y = fmaf(w.w, hv.y, a3.y);
  a3.z = fmaf(w.w, hv.z, a3.z); a3.w = fmaf(w.w, hv.w, a3.w);
}

// ---------------- kernel 2: persistent recurrent kernel ----------------
// 128 CTAs, CTA c owns output columns j0 = 4c .. 4c+3 of BOTH layers.
// thread layout per phase: bt = tid&31 (4 b's), s = tid>>5 (k-slice of 64)
__global__ __launch_bounds__(256, 1) void rec_kernel(
    const int* __restrict__ src, const int* __restrict__ lens,
    const float* __restrict__ Whh0, const float* __restrict__ Wxh1,
    const float* __restrict__ bxh1, const float* __restrict__ Whh1) {
  __shared__ float4 Wsh0[Ht];  // W_hh0[:, j0:j0+4]
  __shared__ float4 Wsh1[Ht];  // W_xh1 slice
  __shared__ float4 Wsh2[Ht];  // W_hh1 slice
  __shared__ float Psh[VCt * 4];
  __shared__ float4 red4[8 * 128];  // [s][jj*32 + bt]
  __shared__ int srcsh[Bt];
  __shared__ int lensh[Bt];
  __shared__ float bsh1[4];
  __shared__ unsigned s_sense;

  const int tid = threadIdx.x;
  const int c = blockIdx.x;
  const int j0 = c * 4;
  float* red = (float*)red4;

  for (int i = tid; i < Ht * 4; i += 256) {
    int k = i >> 2, jj = i & 3;
    ((float*)Wsh0)[i] = Whh0[k * Ht + j0 + jj];
    ((float*)Wsh1)[i] = Wxh1[k * Ht + j0 + jj];
    ((float*)Wsh2)[i] = Whh1[k * Ht + j0 + jj];
  }
  for (int i = tid; i < VCt * 4; i += 256) {
    int v = i >> 2, jj = i & 3;
    Psh[i] = g_P[v * Ht + j0 + jj];
  }
  if (tid < Bt) lensh[tid] = lens[tid];
  if (tid < 4) bsh1[tid] = bxh1[j0 + tid];
  // zero the "previous" (parity-1) buffers for t=0, own columns only
  for (int i = tid; i < 4 * Bt; i += 256) {
    int jj = i >> 7, b = i & 127;
    g_h0[1][(j0 + jj) * Bt + b] = 0.f;
    g_h1[1][(j0 + jj) * Bt + b] = 0.f;
  }
  if (tid == 0) s_sense = *(volatile unsigned*)&g_sense;
  __syncthreads();

#define GBAR()                                              \
  do {                                                      \
    __syncthreads();                                        \
    if (tid == 0) {                                         \
      unsigned ns = s_sense ^ 1u;                           \
      __threadfence();                                      \
      unsigned old = atomicAdd(&g_count, 1u);               \
      if (old == (unsigned)(NCTA - 1)) {                    \
        g_count = 0u;                                       \
        __threadfence();                                    \
        *(volatile unsigned*)&g_sense = ns;                 \
      } else {                                              \
        while (*(volatile unsigned*)&g_sense != ns)         \
          __nanosleep(40);                                  \
      }                                                     \
      __threadfence();                                      \
      s_sense = ns;                                         \
    }                                                       \
    __syncthreads();                                        \
  } while (0)

  GBAR();  // zero-init of h buffers visible to everyone

  const int bt = tid & 31;  // b0 = 4*bt
  const int s = tid >> 5;   // k-slice
  const int kbase = s * 64;

  for (int t = 0; t < Tt; ++t) {
    const int cur = t & 1, prv = cur ^ 1;
    const float* h0p = g_h0[prv];
    float* h0c = g_h0[cur];
    const float* h1p = g_h1[prv];
    float* h1c = g_h1[cur];

    if (tid < Bt) srcsh[tid] = src[tid * Tt + t];

    // ---- phase 1: a0 = P[tok] + h0_prev @ W_hh0 ----
    {
      const float4* hp = (const float4*)h0p;
      float4 a0 = make_float4(0, 0, 0, 0), a1 = a0, a2 = a0, a3 = a0;
#pragma unroll 8
      for (int kk = 0; kk < 64; ++kk) {
        int k = kbase + kk;
        float4 hv = hp[k * 32 + bt];
        float4 w = Wsh0[k];
        fma16(a0, a1, a2, a3, w, hv);
      }
      red4[s * 128 + 0 * 32 + bt] = a0;
      red4[s * 128 + 1 * 32 + bt] = a1;
      red4[s * 128 + 2 * 32 + bt] = a2;
      red4[s * 128 + 3 * 32 + bt] = a3;
    }
    __syncthreads();
#pragma unroll
    for (int r = 0; r < 2; ++r) {
      int o = tid + r * 256;
      int jj = o >> 7, b = o & 127;
      float sum = 0.f;
#pragma unroll
      for (int s2 = 0; s2 < 8; ++s2) sum += red[s2 * 512 + o];
      sum += Psh[srcsh[b] * 4 + jj];
      float prev = h0p[(j0 + jj) * Bt + b];
      float nv = (t < lensh[b]) ? tanhf(sum) : prev;
      h0c[(j0 + jj) * Bt + b] = nv;
    }
    GBAR();  // h0(t) fully visible

    // ---- phase 2: a1 = b1 + h0(t) @ W_xh1 + h1_prev @ W_hh1 ----
    {
      const float4* hp0 = (const float4*)h0c;
      const float4* hp1 = (const float4*)h1p;
      float4 a0 = make_float4(0, 0, 0, 0), a1 = a0, a2 = a0, a3 = a0;
#pragma unroll 8
      for (int kk = 0; kk < 64; ++kk) {
        int k = kbase + kk;
        float4 hv = hp0[k * 32 + bt];
        float4 w = Wsh1[k];
        fma16(a0, a1, a2, a3, w, hv);
      }
#pragma unroll 8
      for (int kk = 0; kk < 64; ++kk) {
        int k = kbase + kk;
        float4 hv = hp1[k * 32 + bt];
        float4 w = Wsh2[k];
        fma16(a0, a1, a2, a3, w, hv);
      }
      red4[s * 128 + 0 * 32 + bt] = a0;
      red4[s * 128 + 1 * 32 + bt] = a1;
      red4[s * 128 + 2 * 32 + bt] = a2;
      red4[s * 128 + 3 * 32 + bt] = a3;
    }
    __syncthreads();
    float* ys = g_ysT + (size_t)t * (Ht * Bt);
#pragma unroll
    for (int r = 0; r < 2; ++r) {
      int o = tid + r * 256;
      int jj = o >> 7, b = o & 127;
      float sum = bsh1[jj];
#pragma unroll
      for (int s2 = 0; s2 < 8; ++s2) sum += red[s2 * 512 + o];
      float prev = h1p[(j0 + jj) * Bt + b];
      float nv = (t < lensh[b]) ? tanhf(sum) : prev;
      h1c[(j0 + jj) * Bt + b] = nv;
      ys[(j0 + jj) * Bt + b] = nv;
    }
    __syncthreads();  // protect srcsh / red for next step
  }
#undef GBAR
}

// ---------------- kernel 3: logits = ys @ fc_w + fc_b ----------------
// grid (2 p-tiles, 512 t). Block computes 128b x 64p, K=512.
__global__ __launch_bounds__(256) void fc_kernel(const float* __restrict__ fcw,
                                                 const float* __restrict__ fcb,
                                                 float* __restrict__ out) {
  __shared__ float4 Ash[32 * 32];  // [kk][b4]  (32 k x 128 b)
  __shared__ float4 Bsh[32 * 16];  // [kk][p4]  (32 k x 64 p)
  const int t = blockIdx.y;
  const int pt = blockIdx.x;  // 0..1
  const int tid = threadIdx.x;
  const int pq = tid & 15;  // 4 p's
  const int bq = tid >> 4;  // 8 b's
  const float4* ys4 = (const float4*)g_ysT + (size_t)t * (Ht * Bt / 4);
  const float4* w4 = (const float4*)fcw;

  float4 acc[8];
#pragma unroll
  for (int i = 0; i < 8; ++i) acc[i] = make_float4(0, 0, 0, 0);

  for (int k0 = 0; k0 < Ht; k0 += 32) {
#pragma unroll
    for (int i = 0; i < 4; ++i) {
      int idx = tid + i * 256;  // 1024 float4
      int kk = idx >> 5, b4 = idx & 31;
      Ash[idx] = ys4[(k0 + kk) * 32 + b4];
    }
#pragma unroll
    for (int i = 0; i < 2; ++i) {
      int idx = tid + i * 256;  // 512 float4
      int kk = idx >> 4, p4 = idx & 15;
      Bsh[idx] = w4[(k0 + kk) * (VPt / 4) + pt * 16 + p4];
    }
    __syncthreads();
#pragma unroll
    for (int kk = 0; kk < 32; ++kk) {
      float4 wv = Bsh[kk * 16 + pq];
      float4 hA = Ash[kk * 32 + bq * 2];
      float4 hB = Ash[kk * 32 + bq * 2 + 1];
      float hb[8] = {hA.x, hA.y, hA.z, hA.w, hB.x, hB.y, hB.z, hB.w};
#pragma unroll
      for (int i = 0; i < 8; ++i) {
        acc[i].x = fmaf(hb[i], wv.x, acc[i].x);
        acc[i].y = fmaf(hb[i], wv.y, acc[i].y);
        acc[i].z = fmaf(hb[i], wv.z, acc[i].z);
        acc[i].w = fmaf(hb[i], wv.w, acc[i].w);
      }
    }
    __syncthreads();
  }
  float4 bv = ((const float4*)fcb)[pt * 16 + pq];
  float4* out4 = (float4*)out;
#pragma unroll
  for (int i = 0; i < 8; ++i) {
    int b = bq * 8 + i;
    float4 v;
    v.x = acc[i].x + bv.x;
    v.y = acc[i].y + bv.y;
    v.z = acc[i].z + bv.z;
    v.w = acc[i].w + bv.w;
    out4[((size_t)b * Tt + t) * (VPt / 4) + pt * 16 + pq] = v;
  }
}

extern "C" void kernel_launch(void* const* d_in, const int* in_sizes, int n_in,
                              void* d_out, int out_size) {
  const int* src = (const int*)d_in[0];
  const int* lens = (const int*)d_in[1];
  const float* emb = (const float*)d_in[2];
  const float* Wxh0 = (const float*)d_in[3];
  const float* bxh0 = (const float*)d_in[4];
  const float* Whh0 = (const float*)d_in[5];
  const float* Wxh1 = (const float*)d_in[6];
  const float* bxh1 = (const float*)d_in[7];
  const float* Whh1 = (const float*)d_in[8];
  const float* fcw = (const float*)d_in[9];
  const float* fcb = (const float*)d_in[10];

  proj_kernel<<<VCt, 128>>>(emb, Wxh0, bxh0);
  rec_kernel<<<NCTA, 256>>>(src, lens, Whh0, Wxh1, bxh1, Whh1);
  fc_kernel<<<dim3(2, Tt), 256>>>(fcw, fcb, (float*)d_out);
}